// round 12
// baseline (speedup 1.0000x reference)
#include <cuda_runtime.h>
#include <math.h>
#include <cfloat>
#include <stdint.h>

#define T_TOK 2048
#define HID   2048
#define NE_OLD 128
#define NE     48
#define TOPK   8
#define INTER  768
#define CAPCT  768

// ---------------- scratch (device globals; no allocation allowed) ----------
__device__ float d_logits[T_TOK * NE_OLD];
__device__ int   d_counts[NE];
__device__ int   d_slot_token[NE * CAPCT];
__device__ int   d_sel_idx[T_TOK * TOPK];
__device__ float d_sel_w[T_TOK * TOPK];
__device__ float d_hbuf[(size_t)NE * CAPCT * INTER];   // 113 MB
__device__ float d_ybuf[(size_t)NE * CAPCT * HID];     // 302 MB

// ======================= helpers (plain sm_103-legal) ======================
__device__ __forceinline__ uint32_t f2tf32(float f) {
    uint32_t r;
    asm("cvt.rna.tf32.f32 %0, %1;" : "=r"(r) : "f"(f));
    return r;
}
__device__ __forceinline__ void mma_tf32(float* c, const uint32_t* a, const uint32_t* b) {
    asm volatile(
        "mma.sync.aligned.m16n8k8.row.col.f32.tf32.tf32.f32 "
        "{%0,%1,%2,%3}, {%4,%5,%6,%7}, {%8,%9}, {%0,%1,%2,%3};"
        : "+f"(c[0]), "+f"(c[1]), "+f"(c[2]), "+f"(c[3])
        : "r"(a[0]), "r"(a[1]), "r"(a[2]), "r"(a[3]), "r"(b[0]), "r"(b[1]));
}
__device__ __forceinline__ uint32_t smem_u32(const void* p) {
    uint32_t a;
    asm("{ .reg .u64 t; cvta.to.shared.u64 t, %1; cvt.u32.u64 %0, t; }" : "=r"(a) : "l"(p));
    return a;
}
template <int IMM>
__device__ __forceinline__ void cp16i(uint32_t s, const void* g) {
    asm volatile("cp.async.ca.shared.global [%0+%2], [%1], 16;" :: "r"(s), "l"(g), "n"(IMM));
}
template <int IMM>
__device__ __forceinline__ float4 lds4(uint32_t a) {
    float4 v;
    asm volatile("ld.shared.v4.f32 {%0,%1,%2,%3}, [%4+%5];"
                 : "=f"(v.x), "=f"(v.y), "=f"(v.z), "=f"(v.w) : "r"(a), "n"(IMM));
    return v;
}
#define CP_COMMIT() asm volatile("cp.async.commit_group;" ::: "memory")
#define CP_WAIT0()  asm volatile("cp.async.wait_group 0;" ::: "memory")

#define KC 32                     // K chunk per stage
#define SPAD 48                   // row stride (floats): LDS.128 conflict-free
#define TSTAGE 24576              // 128*SPAD*4 bytes per tile stage
#define BREG   49152              // B-tile region base (2 stages of A)
#define SMEM_BYTES 98304          // As[2] + Bs[2]

// One 16-k group at immediate offset IMM (= buf*TSTAGE + c0*4).
// k-permuted consumption (validated): lane(g,q) float4 covers k=4q..4q+3.
template <int IMM>
__device__ __forceinline__ void frag_group(const uint32_t* aad, const uint32_t* bad,
                                           float (&acc)[4][4][4]) {
    float4 va[8], vb[4];
#pragma unroll
    for (int mf = 0; mf < 4; mf++) {
        va[2 * mf]     = lds4<IMM>(aad[2 * mf]);
        va[2 * mf + 1] = lds4<IMM>(aad[2 * mf + 1]);
    }
#pragma unroll
    for (int nf = 0; nf < 4; nf++) vb[nf] = lds4<IMM>(bad[nf]);

    uint32_t af[4][4], bf[4][2];
#pragma unroll
    for (int mf = 0; mf < 4; mf++) {
        af[mf][0] = f2tf32(va[2 * mf].x);  af[mf][1] = f2tf32(va[2 * mf + 1].x);
        af[mf][2] = f2tf32(va[2 * mf].y);  af[mf][3] = f2tf32(va[2 * mf + 1].y);
    }
#pragma unroll
    for (int nf = 0; nf < 4; nf++) { bf[nf][0] = f2tf32(vb[nf].x); bf[nf][1] = f2tf32(vb[nf].y); }
#pragma unroll
    for (int mf = 0; mf < 4; mf++)
#pragma unroll
        for (int nf = 0; nf < 4; nf++) mma_tf32(acc[mf][nf], af[mf], bf[nf]);
#pragma unroll
    for (int mf = 0; mf < 4; mf++) {
        af[mf][0] = f2tf32(va[2 * mf].z);  af[mf][1] = f2tf32(va[2 * mf + 1].z);
        af[mf][2] = f2tf32(va[2 * mf].w);  af[mf][3] = f2tf32(va[2 * mf + 1].w);
    }
#pragma unroll
    for (int nf = 0; nf < 4; nf++) { bf[nf][0] = f2tf32(vb[nf].z); bf[nf][1] = f2tf32(vb[nf].w); }
#pragma unroll
    for (int mf = 0; mf < 4; mf++)
#pragma unroll
        for (int nf = 0; nf < 4; nf++) mma_tf32(acc[mf][nf], af[mf], bf[nf]);
}

// ---------------- 1) gating logits (fp32 exact — selection must be stable) -
__global__ void __launch_bounds__(256) gating_kernel(const float* __restrict__ x,
                                                     const float* __restrict__ gw)
{
    __shared__ float Xs[32][33];
    __shared__ float Gs[32][33];
    int tid = threadIdx.x;
    if (blockIdx.x == 0 && blockIdx.y == 0 && tid < NE) d_counts[tid] = 0;

    int t0 = blockIdx.x * 32;
    int e0 = blockIdx.y * 32;
    int ty = tid / 16, tx = tid % 16;
    int lr = tid >> 3;
    int lk = (tid & 7) * 4;

    float acc00 = 0.f, acc01 = 0.f, acc10 = 0.f, acc11 = 0.f;

    for (int k0 = 0; k0 < HID; k0 += 32) {
        float4 xv = *(const float4*)&x[(size_t)(t0 + lr) * HID + k0 + lk];
        float4 gv = *(const float4*)&gw[(size_t)(e0 + lr) * HID + k0 + lk];
        __syncthreads();
        Xs[lk + 0][lr] = xv.x; Xs[lk + 1][lr] = xv.y; Xs[lk + 2][lr] = xv.z; Xs[lk + 3][lr] = xv.w;
        Gs[lk + 0][lr] = gv.x; Gs[lk + 1][lr] = gv.y; Gs[lk + 2][lr] = gv.z; Gs[lk + 3][lr] = gv.w;
        __syncthreads();
#pragma unroll
        for (int k = 0; k < 32; k++) {
            float a0 = Xs[k][ty * 2], a1 = Xs[k][ty * 2 + 1];
            float b0 = Gs[k][tx * 2], b1 = Gs[k][tx * 2 + 1];
            acc00 += a0 * b0; acc01 += a0 * b1;
            acc10 += a1 * b0; acc11 += a1 * b1;
        }
    }
    int t = t0 + ty * 2, e = e0 + tx * 2;
    d_logits[(size_t)(t + 0) * NE_OLD + e + 0] = acc00;
    d_logits[(size_t)(t + 0) * NE_OLD + e + 1] = acc01;
    d_logits[(size_t)(t + 1) * NE_OLD + e + 0] = acc10;
    d_logits[(size_t)(t + 1) * NE_OLD + e + 1] = acc11;
}

// ---------------- 2) routing ----------------------------------------------
__global__ void __launch_bounds__(256) routing_kernel(const int* __restrict__ o2n)
{
    int warp = threadIdx.x >> 5;
    int lane = threadIdx.x & 31;
    int token = blockIdx.x * 8 + warp;

    float v[4];
#pragma unroll
    for (int j = 0; j < 4; j++) {
        int ee = lane + j * 32;
        float lv = d_logits[(size_t)token * NE_OLD + ee];
        v[j] = (o2n[ee] >= 0) ? lv : -FLT_MAX;
    }

    float topv[TOPK];
    int   tope[TOPK];
#pragma unroll
    for (int it = 0; it < TOPK; it++) {
        float bv = v[0]; int be = lane;
#pragma unroll
        for (int j = 1; j < 4; j++) {
            int ee = lane + j * 32;
            if (v[j] > bv || (v[j] == bv && ee < be)) { bv = v[j]; be = ee; }
        }
#pragma unroll
        for (int off = 16; off; off >>= 1) {
            float ov = __shfl_xor_sync(0xffffffffu, bv, off);
            int   oe = __shfl_xor_sync(0xffffffffu, be, off);
            if (ov > bv || (ov == bv && oe < be)) { bv = ov; be = oe; }
        }
        topv[it] = bv; tope[it] = be;
        int wj = be >> 5;
#pragma unroll
        for (int j = 0; j < 4; j++)
            if (wj == j && (be & 31) == lane) v[j] = -FLT_MAX;
    }

    float m = topv[0];
    float w[TOPK];
    float s = 0.f;
#pragma unroll
    for (int i = 0; i < TOPK; i++) { w[i] = expf(topv[i] - m); s += w[i]; }
    float inv = 1.f / s;

    if (lane < TOPK) {
        int i = lane;
        float wi = 0.f;
        int enew = 0;
#pragma unroll
        for (int j = 0; j < TOPK; j++) if (j == i) { wi = w[j] * inv; enew = o2n[tope[j]]; }
        int pos = atomicAdd(&d_counts[enew], 1);
        int sidx = 0; float sw = 0.f;
        if (pos < CAPCT) {
            d_slot_token[enew * CAPCT + pos] = token;
            sidx = enew * CAPCT + pos;
            sw = wi;
        }
        d_sel_idx[token * TOPK + i] = sidx;
        d_sel_w[token * TOPK + i] = sw;
    }
}

// ---------------- 3) GEMM1 (tf32 mma.sync, cp.async, imm-addressed) + SiLU -
__global__ void __launch_bounds__(256, 2) gemm1_mma(const float* __restrict__ x,
                                                    const float* __restrict__ gup)
{
    extern __shared__ char smem[];
    __shared__ int toks[128];
    const uint32_t sb = smem_u32(smem);

    int e = blockIdx.z;
    int cnt = min(d_counts[e], CAPCT);
    int m0 = blockIdx.y * 128;
    if (m0 >= cnt) return;
    int n0 = blockIdx.x * 64;
    int tid = threadIdx.x;
    int wid = tid >> 5, lane = tid & 31;
    int wm = wid >> 2, wn = wid & 3;
    int g = lane >> 2, q = lane & 3;

    if (tid < 128) {
        int m = m0 + tid;
        toks[tid] = d_slot_token[e * CAPCT + ((m < cnt) ? m : 0)];
    }
    __syncthreads();

    // loader: 4 float4 per thread per tile; dest addrs fixed, src ptrs advance
    const float* pA[4];
    const float* pB[4];
    uint32_t sA[4], sB[4];
#pragma unroll
    for (int j = 0; j < 4; j++) {
        int idx = tid + j * 256;
        int r = idx >> 3;
        int qf = (idx & 7) * 4;
        uint32_t so = (uint32_t)(r * SPAD + qf) * 4u;
        sA[j] = sb + so;
        sB[j] = sb + BREG + so;
        int w = r >> 5, l = r & 31;
        int grow = (l < 16) ? (n0 + w * 16 + l) : (768 + n0 + w * 16 + (l - 16));
        pB[j] = gup + (size_t)e * 1536 * HID + (size_t)grow * HID + qf;
        pA[j] = x + (size_t)toks[r] * HID + qf;
    }

    // fragment smem addresses (12 per thread, computed once)
    uint32_t aad[8], bad[4];
#pragma unroll
    for (int mf = 0; mf < 4; mf++) {
        int r = wm * 64 + mf * 16 + g;
        aad[2 * mf]     = sb + (uint32_t)(r * SPAD + 4 * q) * 4u;
        aad[2 * mf + 1] = aad[2 * mf] + 8 * SPAD * 4;
    }
#pragma unroll
    for (int nf = 0; nf < 4; nf++)
        bad[nf] = sb + BREG + (uint32_t)((wn * 32 + nf * 8 + g) * SPAD + 4 * q) * 4u;

    float acc[4][4][4];
#pragma unroll
    for (int i = 0; i < 4; i++)
#pragma unroll
        for (int jn = 0; jn < 4; jn++)
#pragma unroll
            for (int c = 0; c < 4; c++) acc[i][jn][c] = 0.f;

    // prologue: chunk 0 -> buf0
#pragma unroll
    for (int j = 0; j < 4; j++) { cp16i<0>(sA[j], pA[j]); cp16i<0>(sB[j], pB[j]); }
    CP_COMMIT();
#pragma unroll
    for (int j = 0; j < 4; j++) { pA[j] += KC; pB[j] += KC; }

    const int PAIRS = (HID / KC) / 2;   // 32
    for (int ii = 0; ii < PAIRS; ii++) {
        CP_WAIT0();
        __syncthreads();
        // issue chunk 2ii+1 -> buf1 (overlaps compute of buf0)
#pragma unroll
        for (int j = 0; j < 4; j++) { cp16i<TSTAGE>(sA[j], pA[j]); cp16i<TSTAGE>(sB[j], pB[j]); }
        CP_COMMIT();
#pragma unroll
        for (int j = 0; j < 4; j++) { pA[j] += KC; pB[j] += KC; }
        frag_group<0>(aad, bad, acc);
        frag_group<64>(aad, bad, acc);

        CP_WAIT0();
        __syncthreads();
        if (ii + 1 < PAIRS) {
#pragma unroll
            for (int j = 0; j < 4; j++) { cp16i<0>(sA[j], pA[j]); cp16i<0>(sB[j], pB[j]); }
            CP_COMMIT();
#pragma unroll
            for (int j = 0; j < 4; j++) { pA[j] += KC; pB[j] += KC; }
        }
        frag_group<TSTAGE>(aad, bad, acc);
        frag_group<TSTAGE + 64>(aad, bad, acc);
    }

    // epilogue: frags nf 0..1 = gate cols, nf+2 = matching up cols. SiLU in regs.
#pragma unroll
    for (int mf = 0; mf < 4; mf++) {
#pragma unroll
        for (int nf = 0; nf < 2; nf++) {
#pragma unroll
            for (int half = 0; half < 2; half++) {
                int m = m0 + wm * 64 + mf * 16 + g + half * 8;
                if (m < cnt) {
                    float g0 = acc[mf][nf][half * 2 + 0];
                    float g1 = acc[mf][nf][half * 2 + 1];
                    float u0 = acc[mf][nf + 2][half * 2 + 0];
                    float u1 = acc[mf][nf + 2][half * 2 + 1];
                    float2 h;
                    h.x = g0 / (1.f + __expf(-g0)) * u0;
                    h.y = g1 / (1.f + __expf(-g1)) * u1;
                    int col = n0 + 16 * wn + 8 * nf + 2 * q;
                    *(float2*)&d_hbuf[((size_t)e * CAPCT + m) * INTER + col] = h;
                }
            }
        }
    }
}

// ---------------- 4) GEMM2 (tf32 mma.sync, cp.async, imm-addressed) --------
__global__ void __launch_bounds__(256, 2) gemm2_mma(const float* __restrict__ down)
{
    extern __shared__ char smem[];
    const uint32_t sb = smem_u32(smem);

    int e = blockIdx.z;
    int cnt = min(d_counts[e], CAPCT);
    int m0 = blockIdx.y * 128;
    if (m0 >= cnt) return;
    int n0 = blockIdx.x * 128;
    int tid = threadIdx.x;
    int wid = tid >> 5, lane = tid & 31;
    int wm = wid >> 2, wn = wid & 3;
    int g = lane >> 2, q = lane & 3;

    const float* pA[4];
    const float* pB[4];
    uint32_t sA[4], sB[4];
#pragma unroll
    for (int j = 0; j < 4; j++) {
        int idx = tid + j * 256;
        int r = idx >> 3;
        int qf = (idx & 7) * 4;
        uint32_t so = (uint32_t)(r * SPAD + qf) * 4u;
        sA[j] = sb + so;
        sB[j] = sb + BREG + so;
        pA[j] = d_hbuf + ((size_t)e * CAPCT + m0 + r) * INTER + qf;
        pB[j] = down + (size_t)e * HID * INTER + (size_t)(n0 + r) * INTER + qf;
    }

    uint32_t aad[8], bad[4];
#pragma unroll
    for (int mf = 0; mf < 4; mf++) {
        int r = wm * 64 + mf * 16 + g;
        aad[2 * mf]     = sb + (uint32_t)(r * SPAD + 4 * q) * 4u;
        aad[2 * mf + 1] = aad[2 * mf] + 8 * SPAD * 4;
    }
#pragma unroll
    for (int nf = 0; nf < 4; nf++)
        bad[nf] = sb + BREG + (uint32_t)((wn * 32 + nf * 8 + g) * SPAD + 4 * q) * 4u;

    float acc[4][4][4];
#pragma unroll
    for (int i = 0; i < 4; i++)
#pragma unroll
        for (int jn = 0; jn < 4; jn++)
#pragma unroll
            for (int c = 0; c < 4; c++) acc[i][jn][c] = 0.f;

#pragma unroll
    for (int j = 0; j < 4; j++) { cp16i<0>(sA[j], pA[j]); cp16i<0>(sB[j], pB[j]); }
    CP_COMMIT();
#pragma unroll
    for (int j = 0; j < 4; j++) { pA[j] += KC; pB[j] += KC; }

    const int PAIRS = (INTER / KC) / 2;   // 12
    for (int ii = 0; ii < PAIRS; ii++) {
        CP_WAIT0();
        __syncthreads();
#pragma unroll
        for (int j = 0; j < 4; j++) { cp16i<TSTAGE>(sA[j], pA[j]); cp16i<TSTAGE>(sB[j], pB[j]); }
        CP_COMMIT();
#pragma unroll
        for (int j = 0; j < 4; j++) { pA[j] += KC; pB[j] += KC; }
        frag_group<0>(aad, bad, acc);
        frag_group<64>(aad, bad, acc);

        CP_WAIT0();
        __syncthreads();
        if (ii + 1 < PAIRS) {
#pragma unroll
            for (int j = 0; j < 4; j++) { cp16i<0>(sA[j], pA[j]); cp16i<0>(sB[j], pB[j]); }
            CP_COMMIT();
#pragma unroll
            for (int j = 0; j < 4; j++) { pA[j] += KC; pB[j] += KC; }
        }
        frag_group<TSTAGE>(aad, bad, acc);
        frag_group<TSTAGE + 64>(aad, bad, acc);
    }

#pragma unroll
    for (int mf = 0; mf < 4; mf++) {
#pragma unroll
        for (int nf = 0; nf < 4; nf++) {
#pragma unroll
            for (int half = 0; half < 2; half++) {
                int m = m0 + wm * 64 + mf * 16 + g + half * 8;
                if (m < cnt) {
                    float2 yv;
                    yv.x = acc[mf][nf][half * 2 + 0];
                    yv.y = acc[mf][nf][half * 2 + 1];
                    int col = n0 + 32 * wn + 8 * nf + 2 * q;
                    *(float2*)&d_ybuf[((size_t)e * CAPCT + m) * HID + col] = yv;
                }
            }
        }
    }
}

// ---------------- 5) combine ----------------------------------------------
__global__ void __launch_bounds__(256) gather_kernel(float* __restrict__ out)
{
    int t = blockIdx.x;
    __shared__ int  sidx[TOPK];
    __shared__ float sw[TOPK];
    if (threadIdx.x < TOPK) {
        sidx[threadIdx.x] = d_sel_idx[t * TOPK + threadIdx.x];
        sw[threadIdx.x]   = d_sel_w[t * TOPK + threadIdx.x];
    }
    __syncthreads();

    const float4* yb = (const float4*)d_ybuf;
    float4* o = (float4*)(out + (size_t)t * HID);
#pragma unroll
    for (int v = threadIdx.x; v < HID / 4; v += 256) {
        float4 acc = {0.f, 0.f, 0.f, 0.f};
#pragma unroll
        for (int k = 0; k < TOPK; k++) {
            float4 yv = yb[(size_t)sidx[k] * (HID / 4) + v];
            float wk = sw[k];
            acc.x += wk * yv.x; acc.y += wk * yv.y;
            acc.z += wk * yv.z; acc.w += wk * yv.w;
        }
        o[v] = acc;
    }
}

// ---------------- launch ---------------------------------------------------
extern "C" void kernel_launch(void* const* d_in, const int* in_sizes, int n_in,
                              void* d_out, int out_size)
{
    const float* x    = (const float*)d_in[0];   // hidden_states [2,1024,2048]
    const float* gw   = (const float*)d_in[1];   // gate_weight [128,2048]
    const float* gup  = (const float*)d_in[2];   // gate_up_proj [48,1536,2048]
    const float* down = (const float*)d_in[3];   // down_proj [48,2048,768]
    const int*   o2n  = (const int*)d_in[4];     // old_to_new [128]

    cudaFuncSetAttribute(gemm1_mma, cudaFuncAttributeMaxDynamicSharedMemorySize, SMEM_BYTES);
    cudaFuncSetAttribute(gemm2_mma, cudaFuncAttributeMaxDynamicSharedMemorySize, SMEM_BYTES);

    gating_kernel<<<dim3(T_TOK / 32, NE_OLD / 32), 256>>>(x, gw);
    routing_kernel<<<T_TOK / 8, 256>>>(o2n);
    gemm1_mma<<<dim3(INTER / 64, CAPCT / 128, NE), 256, SMEM_BYTES>>>(x, gup);
    gemm2_mma<<<dim3(HID / 128, CAPCT / 128, NE), 256, SMEM_BYTES>>>(down);
    gather_kernel<<<T_TOK, 256>>>((float*)d_out);
}

// round 14
// speedup vs baseline: 1.8096x; 1.8096x over previous
#include <cuda_runtime.h>
#include <math.h>
#include <cfloat>
#include <stdint.h>

#define T_TOK 2048
#define HID   2048
#define NE_OLD 128
#define NE     48
#define TOPK   8
#define INTER  768
#define CAPCT  768

// ---------------- scratch (device globals; no allocation allowed) ----------
__device__ float d_logits[T_TOK * NE_OLD];
__device__ int   d_counts[NE];
__device__ int   d_slot_token[NE * CAPCT];
__device__ int   d_sel_idx[T_TOK * TOPK];
__device__ float d_sel_w[T_TOK * TOPK];
__device__ float d_hbuf[(size_t)NE * CAPCT * INTER];   // 113 MB
__device__ float d_ybuf[(size_t)NE * CAPCT * HID];     // 302 MB

// ======================= helpers (plain sm_103-legal) ======================
__device__ __forceinline__ uint32_t f2tf32(float f) {
    uint32_t r;
    asm("cvt.rna.tf32.f32 %0, %1;" : "=r"(r) : "f"(f));
    return r;
}
__device__ __forceinline__ void mma_tf32(float* c, const uint32_t* a, const uint32_t* b) {
    asm volatile(
        "mma.sync.aligned.m16n8k8.row.col.f32.tf32.tf32.f32 "
        "{%0,%1,%2,%3}, {%4,%5,%6,%7}, {%8,%9}, {%0,%1,%2,%3};"
        : "+f"(c[0]), "+f"(c[1]), "+f"(c[2]), "+f"(c[3])
        : "r"(a[0]), "r"(a[1]), "r"(a[2]), "r"(a[3]), "r"(b[0]), "r"(b[1]));
}
__device__ __forceinline__ uint32_t smem_u32(const void* p) {
    uint32_t a;
    asm("{ .reg .u64 t; cvta.to.shared.u64 t, %1; cvt.u32.u64 %0, t; }" : "=r"(a) : "l"(p));
    return a;
}
__device__ __forceinline__ void cp16(uint32_t s, const void* g) {
    asm volatile("cp.async.ca.shared.global [%0], [%1], 16;" :: "r"(s), "l"(g));
}
#define CP_COMMIT() asm volatile("cp.async.commit_group;" ::: "memory")
#define CP_WAIT0()  asm volatile("cp.async.wait_group 0;" ::: "memory")

#define KC 32                     // K chunk per stage
#define SPAD 36                   // 32 + 4 pad floats: frag LDS conflict-free
#define TSTA (128 * SPAD * 4)     // A stage bytes (18432)
#define TSTB (256 * SPAD * 4)     // B stage bytes (36864)
#define BBASE (2 * TSTA)          // B region base
#define SMEM_BYTES (2 * TSTA + 2 * TSTB)   // 110592

// Per-kk fragment compute for a 64x64 warp tile (acc[4][8][4]).
__device__ __forceinline__ void frag_kk(const float* __restrict__ Asb,
                                        const float* __restrict__ Bsb,
                                        int kb, int wm, int wn, int g, int q,
                                        float (&acc)[4][8][4])
{
    uint32_t afrag[4][4], bfrag[8][2];
#pragma unroll
    for (int mf = 0; mf < 4; mf++) {
        int r = wm * 64 + mf * 16;
        afrag[mf][0] = f2tf32(Asb[(r + g    ) * SPAD + kb + q    ]);
        afrag[mf][1] = f2tf32(Asb[(r + g + 8) * SPAD + kb + q    ]);
        afrag[mf][2] = f2tf32(Asb[(r + g    ) * SPAD + kb + q + 4]);
        afrag[mf][3] = f2tf32(Asb[(r + g + 8) * SPAD + kb + q + 4]);
    }
#pragma unroll
    for (int nf = 0; nf < 8; nf++) {
        int r = wn * 64 + nf * 8 + g;
        bfrag[nf][0] = f2tf32(Bsb[r * SPAD + kb + q    ]);
        bfrag[nf][1] = f2tf32(Bsb[r * SPAD + kb + q + 4]);
    }
#pragma unroll
    for (int mf = 0; mf < 4; mf++)
#pragma unroll
        for (int nf = 0; nf < 8; nf++)
            mma_tf32(acc[mf][nf], afrag[mf], bfrag[nf]);
}

// ---------------- 1) gating logits (fp32 exact — selection must be stable) -
__global__ void __launch_bounds__(256) gating_kernel(const float* __restrict__ x,
                                                     const float* __restrict__ gw)
{
    __shared__ float Xs[32][33];
    __shared__ float Gs[32][33];
    int tid = threadIdx.x;
    if (blockIdx.x == 0 && blockIdx.y == 0 && tid < NE) d_counts[tid] = 0;

    int t0 = blockIdx.x * 32;
    int e0 = blockIdx.y * 32;
    int ty = tid / 16, tx = tid % 16;
    int lr = tid >> 3;
    int lk = (tid & 7) * 4;

    float acc00 = 0.f, acc01 = 0.f, acc10 = 0.f, acc11 = 0.f;

    for (int k0 = 0; k0 < HID; k0 += 32) {
        float4 xv = *(const float4*)&x[(size_t)(t0 + lr) * HID + k0 + lk];
        float4 gv = *(const float4*)&gw[(size_t)(e0 + lr) * HID + k0 + lk];
        __syncthreads();
        Xs[lk + 0][lr] = xv.x; Xs[lk + 1][lr] = xv.y; Xs[lk + 2][lr] = xv.z; Xs[lk + 3][lr] = xv.w;
        Gs[lk + 0][lr] = gv.x; Gs[lk + 1][lr] = gv.y; Gs[lk + 2][lr] = gv.z; Gs[lk + 3][lr] = gv.w;
        __syncthreads();
#pragma unroll
        for (int k = 0; k < 32; k++) {
            float a0 = Xs[k][ty * 2], a1 = Xs[k][ty * 2 + 1];
            float b0 = Gs[k][tx * 2], b1 = Gs[k][tx * 2 + 1];
            acc00 += a0 * b0; acc01 += a0 * b1;
            acc10 += a1 * b0; acc11 += a1 * b1;
        }
    }
    int t = t0 + ty * 2, e = e0 + tx * 2;
    d_logits[(size_t)(t + 0) * NE_OLD + e + 0] = acc00;
    d_logits[(size_t)(t + 0) * NE_OLD + e + 1] = acc01;
    d_logits[(size_t)(t + 1) * NE_OLD + e + 0] = acc10;
    d_logits[(size_t)(t + 1) * NE_OLD + e + 1] = acc11;
}

// ---------------- 2) routing ----------------------------------------------
__global__ void __launch_bounds__(256) routing_kernel(const int* __restrict__ o2n)
{
    int warp = threadIdx.x >> 5;
    int lane = threadIdx.x & 31;
    int token = blockIdx.x * 8 + warp;

    float v[4];
#pragma unroll
    for (int j = 0; j < 4; j++) {
        int ee = lane + j * 32;
        float lv = d_logits[(size_t)token * NE_OLD + ee];
        v[j] = (o2n[ee] >= 0) ? lv : -FLT_MAX;
    }

    float topv[TOPK];
    int   tope[TOPK];
#pragma unroll
    for (int it = 0; it < TOPK; it++) {
        float bv = v[0]; int be = lane;
#pragma unroll
        for (int j = 1; j < 4; j++) {
            int ee = lane + j * 32;
            if (v[j] > bv || (v[j] == bv && ee < be)) { bv = v[j]; be = ee; }
        }
#pragma unroll
        for (int off = 16; off; off >>= 1) {
            float ov = __shfl_xor_sync(0xffffffffu, bv, off);
            int   oe = __shfl_xor_sync(0xffffffffu, be, off);
            if (ov > bv || (ov == bv && oe < be)) { bv = ov; be = oe; }
        }
        topv[it] = bv; tope[it] = be;
        int wj = be >> 5;
#pragma unroll
        for (int j = 0; j < 4; j++)
            if (wj == j && (be & 31) == lane) v[j] = -FLT_MAX;
    }

    float m = topv[0];
    float w[TOPK];
    float s = 0.f;
#pragma unroll
    for (int i = 0; i < TOPK; i++) { w[i] = expf(topv[i] - m); s += w[i]; }
    float inv = 1.f / s;

    if (lane < TOPK) {
        int i = lane;
        float wi = 0.f;
        int enew = 0;
#pragma unroll
        for (int j = 0; j < TOPK; j++) if (j == i) { wi = w[j] * inv; enew = o2n[tope[j]]; }
        int pos = atomicAdd(&d_counts[enew], 1);
        int sidx = 0; float sw = 0.f;
        if (pos < CAPCT) {
            d_slot_token[enew * CAPCT + pos] = token;
            sidx = enew * CAPCT + pos;
            sw = wi;
        }
        d_sel_idx[token * TOPK + i] = sidx;
        d_sel_w[token * TOPK + i] = sw;
    }
}

// ---------------- 3) GEMM1 (tf32 mma.sync, 64x64 warp tiles) + SiLU --------
// Block: M=128 x 256 concat cols (gate 128 ++ up 128, 32-col interleave).
// 8 warps 2(M) x 4(N); warp tile 64x64. Warp wn: nf 0-3 gate, nf 4-7 up.
__global__ void __launch_bounds__(256) gemm1_mma(const float* __restrict__ x,
                                                 const float* __restrict__ gup)
{
    extern __shared__ char smem[];
    __shared__ int toks[128];
    const uint32_t sb = smem_u32(smem);

    int e = blockIdx.z;
    int cnt = min(d_counts[e], CAPCT);
    int m0 = blockIdx.y * 128;
    if (m0 >= cnt) return;
    int n0 = blockIdx.x * 128;          // gate-col base (up cols mirror at +768)
    int tid = threadIdx.x;
    int wid = tid >> 5, lane = tid & 31;
    int wm = wid >> 2, wn = wid & 3;
    int g = lane >> 2, q = lane & 3;

    if (tid < 128) {
        int m = m0 + tid;
        toks[tid] = d_slot_token[e * CAPCT + ((m < cnt) ? m : 0)];
    }
    __syncthreads();

    // loaders: A 4 float4/thread (128 rows), B 8 float4/thread (256 rows)
    const float* asrc[4]; uint32_t sA[4];
    const float* bsrc[8]; uint32_t sB[8];
#pragma unroll
    for (int j = 0; j < 4; j++) {
        int idx = tid + j * 256;
        int r = idx >> 3, qf = (idx & 7) * 4;
        sA[j] = sb + (uint32_t)(r * SPAD + qf) * 4u;
        asrc[j] = x + (size_t)toks[r] * HID + qf;
    }
#pragma unroll
    for (int j = 0; j < 8; j++) {
        int idx = tid + j * 256;
        int r = idx >> 3, qf = (idx & 7) * 4;
        sB[j] = sb + BBASE + (uint32_t)(r * SPAD + qf) * 4u;
        int w = r >> 6, l = r & 63;
        int grow = (l < 32) ? (n0 + 32 * w + l) : (768 + n0 + 32 * w + (l - 32));
        bsrc[j] = gup + (size_t)e * 1536 * HID + (size_t)grow * HID + qf;
    }

    float acc[4][8][4];
#pragma unroll
    for (int i = 0; i < 4; i++)
#pragma unroll
        for (int jn = 0; jn < 8; jn++)
#pragma unroll
            for (int c = 0; c < 4; c++) acc[i][jn][c] = 0.f;

    const int NCH = HID / KC;   // 64
#pragma unroll
    for (int j = 0; j < 4; j++) cp16(sA[j], asrc[j]);
#pragma unroll
    for (int j = 0; j < 8; j++) cp16(sB[j], bsrc[j]);
    CP_COMMIT();

    for (int i = 0; i < NCH; i++) {
        int buf = i & 1;
        CP_WAIT0();
        __syncthreads();
        if (i + 1 < NCH) {
            int nb = buf ^ 1;
            int k1 = (i + 1) * KC;
#pragma unroll
            for (int j = 0; j < 4; j++) cp16(sA[j] + nb * TSTA, asrc[j] + k1);
#pragma unroll
            for (int j = 0; j < 8; j++) cp16(sB[j] + nb * TSTB, bsrc[j] + k1);
            CP_COMMIT();
        }
        const float* Asb = (const float*)(smem + buf * TSTA);
        const float* Bsb = (const float*)(smem + BBASE + buf * TSTB);
#pragma unroll
        for (int kk = 0; kk < 4; kk++)
            frag_kk(Asb, Bsb, kk * 8, wm, wn, g, q, acc);
    }

    // epilogue: nf 0-3 gate, nf+4 matching up. SiLU in regs.
#pragma unroll
    for (int mf = 0; mf < 4; mf++) {
#pragma unroll
        for (int nf = 0; nf < 4; nf++) {
#pragma unroll
            for (int half = 0; half < 2; half++) {
                int m = m0 + wm * 64 + mf * 16 + g + half * 8;
                if (m < cnt) {
                    float g0 = acc[mf][nf][half * 2 + 0];
                    float g1 = acc[mf][nf][half * 2 + 1];
                    float u0 = acc[mf][nf + 4][half * 2 + 0];
                    float u1 = acc[mf][nf + 4][half * 2 + 1];
                    float2 h;
                    h.x = g0 / (1.f + __expf(-g0)) * u0;
                    h.y = g1 / (1.f + __expf(-g1)) * u1;
                    int col = n0 + 32 * wn + 8 * nf + 2 * q;
                    *(float2*)&d_hbuf[((size_t)e * CAPCT + m) * INTER + col] = h;
                }
            }
        }
    }
}

// ---------------- 4) GEMM2 (tf32 mma.sync, 64x64 warp tiles) ---------------
// Block: M=128 x N=256, K=768. 8 warps 2x4.
__global__ void __launch_bounds__(256) gemm2_mma(const float* __restrict__ down)
{
    extern __shared__ char smem[];
    const uint32_t sb = smem_u32(smem);

    int e = blockIdx.z;
    int cnt = min(d_counts[e], CAPCT);
    int m0 = blockIdx.y * 128;
    if (m0 >= cnt) return;
    int n0 = blockIdx.x * 256;
    int tid = threadIdx.x;
    int wid = tid >> 5, lane = tid & 31;
    int wm = wid >> 2, wn = wid & 3;
    int g = lane >> 2, q = lane & 3;

    const float* asrc[4]; uint32_t sA[4];
    const float* bsrc[8]; uint32_t sB[8];
#pragma unroll
    for (int j = 0; j < 4; j++) {
        int idx = tid + j * 256;
        int r = idx >> 3, qf = (idx & 7) * 4;
        sA[j] = sb + (uint32_t)(r * SPAD + qf) * 4u;
        asrc[j] = d_hbuf + ((size_t)e * CAPCT + m0 + r) * INTER + qf;
    }
#pragma unroll
    for (int j = 0; j < 8; j++) {
        int idx = tid + j * 256;
        int r = idx >> 3, qf = (idx & 7) * 4;
        sB[j] = sb + BBASE + (uint32_t)(r * SPAD + qf) * 4u;
        bsrc[j] = down + (size_t)e * HID * INTER + (size_t)(n0 + r) * INTER + qf;
    }

    float acc[4][8][4];
#pragma unroll
    for (int i = 0; i < 4; i++)
#pragma unroll
        for (int jn = 0; jn < 8; jn++)
#pragma unroll
            for (int c = 0; c < 4; c++) acc[i][jn][c] = 0.f;

    const int NCH = INTER / KC;  // 24
#pragma unroll
    for (int j = 0; j < 4; j++) cp16(sA[j], asrc[j]);
#pragma unroll
    for (int j = 0; j < 8; j++) cp16(sB[j], bsrc[j]);
    CP_COMMIT();

    for (int i = 0; i < NCH; i++) {
        int buf = i & 1;
        CP_WAIT0();
        __syncthreads();
        if (i + 1 < NCH) {
            int nb = buf ^ 1;
            int k1 = (i + 1) * KC;
#pragma unroll
            for (int j = 0; j < 4; j++) cp16(sA[j] + nb * TSTA, asrc[j] + k1);
#pragma unroll
            for (int j = 0; j < 8; j++) cp16(sB[j] + nb * TSTB, bsrc[j] + k1);
            CP_COMMIT();
        }
        const float* Asb = (const float*)(smem + buf * TSTA);
        const float* Bsb = (const float*)(smem + BBASE + buf * TSTB);
#pragma unroll
        for (int kk = 0; kk < 4; kk++)
            frag_kk(Asb, Bsb, kk * 8, wm, wn, g, q, acc);
    }

#pragma unroll
    for (int mf = 0; mf < 4; mf++) {
#pragma unroll
        for (int nf = 0; nf < 8; nf++) {
#pragma unroll
            for (int half = 0; half < 2; half++) {
                int m = m0 + wm * 64 + mf * 16 + g + half * 8;
                if (m < cnt) {
                    float2 yv;
                    yv.x = acc[mf][nf][half * 2 + 0];
                    yv.y = acc[mf][nf][half * 2 + 1];
                    int col = n0 + 64 * wn + 8 * nf + 2 * q;
                    *(float2*)&d_ybuf[((size_t)e * CAPCT + m) * HID + col] = yv;
                }
            }
        }
    }
}

// ---------------- 5) combine ----------------------------------------------
__global__ void __launch_bounds__(256) gather_kernel(float* __restrict__ out)
{
    int t = blockIdx.x;
    __shared__ int  sidx[TOPK];
    __shared__ float sw[TOPK];
    if (threadIdx.x < TOPK) {
        sidx[threadIdx.x] = d_sel_idx[t * TOPK + threadIdx.x];
        sw[threadIdx.x]   = d_sel_w[t * TOPK + threadIdx.x];
    }
    __syncthreads();

    const float4* yb = (const float4*)d_ybuf;
    float4* o = (float4*)(out + (size_t)t * HID);
#pragma unroll
    for (int v = threadIdx.x; v < HID / 4; v += 256) {
        float4 acc = {0.f, 0.f, 0.f, 0.f};
#pragma unroll
        for (int k = 0; k < TOPK; k++) {
            float4 yv = yb[(size_t)sidx[k] * (HID / 4) + v];
            float wk = sw[k];
            acc.x += wk * yv.x; acc.y += wk * yv.y;
            acc.z += wk * yv.z; acc.w += wk * yv.w;
        }
        o[v] = acc;
    }
}

// ---------------- launch ---------------------------------------------------
extern "C" void kernel_launch(void* const* d_in, const int* in_sizes, int n_in,
                              void* d_out, int out_size)
{
    const float* x    = (const float*)d_in[0];   // hidden_states [2,1024,2048]
    const float* gw   = (const float*)d_in[1];   // gate_weight [128,2048]
    const float* gup  = (const float*)d_in[2];   // gate_up_proj [48,1536,2048]
    const float* down = (const float*)d_in[3];   // down_proj [48,2048,768]
    const int*   o2n  = (const int*)d_in[4];     // old_to_new [128]

    cudaFuncSetAttribute(gemm1_mma, cudaFuncAttributeMaxDynamicSharedMemorySize, SMEM_BYTES);
    cudaFuncSetAttribute(gemm2_mma, cudaFuncAttributeMaxDynamicSharedMemorySize, SMEM_BYTES);

    gating_kernel<<<dim3(T_TOK / 32, NE_OLD / 32), 256>>>(x, gw);
    routing_kernel<<<T_TOK / 8, 256>>>(o2n);
    gemm1_mma<<<dim3(INTER / 128, CAPCT / 128, NE), 256, SMEM_BYTES>>>(x, gup);
    gemm2_mma<<<dim3(HID / 256, CAPCT / 128, NE), 256, SMEM_BYTES>>>(down);
    gather_kernel<<<T_TOK, 256>>>((float*)d_out);
}